// round 8
// baseline (speedup 1.0000x reference)
#include <cuda_runtime.h>
#include <cuda_bf16.h>
#include <mma.h>
#include <cuda_pipeline.h>
#include <math.h>

#define Bn   2
#define Tn   2048
#define Cn   1024
#define Hn   16
#define HD   64
#define NQKV 3072
#define MTOK 4096

// GEMM tiling: 128x128x32, 8 warps, 2 stages
#define A_ELEMS 5120
#define B_ELEMS 4352
#define STAGE_ELEMS (2 * A_ELEMS + 2 * B_ELEMS)
#define GEMM_SMEM (2 * STAGE_ELEMS * 2)

// Attention tiling: P reuses K's buffers; Q frags reloaded per tile.
#define KV_LD 72
#define S_LD  68
#define OFF_QH 0
#define OFF_QL 9216
#define OFF_KH 18432
#define OFF_KL 27648
#define OFF_VH 36864
#define OFF_VL 46080
#define OFF_S  55296
#define OFF_L  72704
#define ATTN2_SMEM 72960

using namespace nvcuda;
typedef wmma::fragment<wmma::matrix_a, 16, 16, 16, __nv_bfloat16, wmma::row_major> FragA;
typedef wmma::fragment<wmma::matrix_b, 16, 16, 16, __nv_bfloat16, wmma::row_major> FragB;
typedef wmma::fragment<wmma::matrix_b, 16, 16, 16, __nv_bfloat16, wmma::col_major> FragBT;
typedef wmma::fragment<wmma::accumulator, 16, 16, 16, float> FragC;

__device__ __nv_bfloat16 g_qkvh[(size_t)MTOK * NQKV];
__device__ __nv_bfloat16 g_qkvl[(size_t)MTOK * NQKV];
__device__ __nv_bfloat16 g_xhi[(size_t)MTOK * Cn];
__device__ __nv_bfloat16 g_xlo[(size_t)MTOK * Cn];
__device__ __nv_bfloat16 g_whi[(size_t)Cn * NQKV];
__device__ __nv_bfloat16 g_wlo[(size_t)Cn * NQKV];
__device__ __nv_bfloat16 g_yhi[(size_t)MTOK * Cn];
__device__ __nv_bfloat16 g_ylo[(size_t)MTOK * Cn];
__device__ __nv_bfloat16 g_phi[(size_t)Cn * Cn];
__device__ __nv_bfloat16 g_plo[(size_t)Cn * Cn];

// ---------------------------------------------------------------------------
__global__ void split_bf16(const float* __restrict__ in,
                           __nv_bfloat16* __restrict__ hi,
                           __nv_bfloat16* __restrict__ lo, int n4)
{
    int i = blockIdx.x * blockDim.x + threadIdx.x;
    if (i >= n4) return;
    float4 v = ((const float4*)in)[i];
    float a0 = v.x;
    float a1 = v.y;
    float a2 = v.z;
    float a3 = v.w;
    __nv_bfloat16 h0 = __float2bfloat16(a0);
    __nv_bfloat16 h1 = __float2bfloat16(a1);
    __nv_bfloat16 h2 = __float2bfloat16(a2);
    __nv_bfloat16 h3 = __float2bfloat16(a3);
    __nv_bfloat16 l0 = __float2bfloat16(a0 - __bfloat162float(h0));
    __nv_bfloat16 l1 = __float2bfloat16(a1 - __bfloat162float(h1));
    __nv_bfloat16 l2 = __float2bfloat16(a2 - __bfloat162float(h2));
    __nv_bfloat16 l3 = __float2bfloat16(a3 - __bfloat162float(h3));
    __nv_bfloat162 hp0, hp1, lp0, lp1;
    hp0.x = h0; hp0.y = h1; hp1.x = h2; hp1.y = h3;
    lp0.x = l0; lp0.y = l1; lp1.x = l2; lp1.y = l3;
    __nv_bfloat162* hi2 = (__nv_bfloat162*)hi;
    __nv_bfloat162* lo2 = (__nv_bfloat162*)lo;
    hi2[2 * i]     = hp0;
    hi2[2 * i + 1] = hp1;
    lo2[2 * i]     = lp0;
    lo2[2 * i + 1] = lp1;
}

// ---------------------------------------------------------------------------
// Shared GEMM machinery (unchanged from round 7)
// ---------------------------------------------------------------------------
__device__ __forceinline__ void g3_prefetch(
    __nv_bfloat16* sm, int stage, int kt,
    const __nv_bfloat16* Ahi, const __nv_bfloat16* Alo,
    const __nv_bfloat16* Bhi, const __nv_bfloat16* Blo,
    int row0, int col0, int N, int K, int tid)
{
    __nv_bfloat16* s0 = sm + stage * STAGE_ELEMS;
    int k0 = kt * 32;
    int c;
    for (c = tid; c < 512; c += 256) {
        int r   = c >> 2;
        int col = (c & 3) * 8;
        const __nv_bfloat16* srch = Ahi + (size_t)(row0 + r) * K + k0 + col;
        const __nv_bfloat16* srcl = Alo + (size_t)(row0 + r) * K + k0 + col;
        __pipeline_memcpy_async(s0 + r * 40 + col, srch, 16);
        __pipeline_memcpy_async(s0 + A_ELEMS + r * 40 + col, srcl, 16);
    }
    for (c = tid; c < 512; c += 256) {
        int r   = c >> 4;
        int col = (c & 15) * 8;
        const __nv_bfloat16* srch = Bhi + (size_t)(k0 + r) * N + col0 + col;
        const __nv_bfloat16* srcl = Blo + (size_t)(k0 + r) * N + col0 + col;
        __pipeline_memcpy_async(s0 + 2 * A_ELEMS + r * 136 + col, srch, 16);
        __pipeline_memcpy_async(s0 + 2 * A_ELEMS + B_ELEMS + r * 136 + col, srcl, 16);
    }
    __pipeline_commit();
}

__device__ __forceinline__ void g3_mainloop(
    __nv_bfloat16* smg, FragC acc[4][2],
    const __nv_bfloat16* Ahi, const __nv_bfloat16* Alo,
    const __nv_bfloat16* Bhi, const __nv_bfloat16* Blo,
    int row0, int col0, int N, int K, int tid, int wm, int wn)
{
    const int nt = K / 32;
    int mi, ni;
    g3_prefetch(smg, 0, 0, Ahi, Alo, Bhi, Blo, row0, col0, N, K, tid);

    for (int kt = 0; kt < nt; kt++) {
        __pipeline_wait_prior(0);
        __syncthreads();
        if (kt + 1 < nt)
            g3_prefetch(smg, (kt + 1) & 1, kt + 1, Ahi, Alo, Bhi, Blo,
                        row0, col0, N, K, tid);

        const __nv_bfloat16* s0 = smg + (kt & 1) * STAGE_ELEMS;
#pragma unroll
        for (int ks = 0; ks < 32; ks += 16) {
            FragA ah[4];
            FragA al[4];
            FragB bh[2];
            FragB bl[2];
#pragma unroll
            for (mi = 0; mi < 4; mi++) {
                const __nv_bfloat16* pa = s0 + (wm + mi * 16) * 40 + ks;
                wmma::load_matrix_sync(ah[mi], pa, 40);
                wmma::load_matrix_sync(al[mi], pa + A_ELEMS, 40);
            }
#pragma unroll
            for (ni = 0; ni < 2; ni++) {
                const __nv_bfloat16* pb = s0 + 2 * A_ELEMS + ks * 136 + wn + ni * 16;
                wmma::load_matrix_sync(bh[ni], pb, 136);
                wmma::load_matrix_sync(bl[ni], pb + B_ELEMS, 136);
            }
#pragma unroll
            for (mi = 0; mi < 4; mi++) {
#pragma unroll
                for (ni = 0; ni < 2; ni++) {
                    wmma::mma_sync(acc[mi][ni], ah[mi], bh[ni], acc[mi][ni]);
                    wmma::mma_sync(acc[mi][ni], ah[mi], bl[ni], acc[mi][ni]);
                    wmma::mma_sync(acc[mi][ni], al[mi], bh[ni], acc[mi][ni]);
                }
            }
        }
    }
}

__global__ __launch_bounds__(256, 2) void gemm_wmma3(
    const __nv_bfloat16* __restrict__ Ahi, const __nv_bfloat16* __restrict__ Alo,
    const __nv_bfloat16* __restrict__ Bhi, const __nv_bfloat16* __restrict__ Blo,
    float* __restrict__ C, int M, int N, int K)
{
    extern __shared__ __nv_bfloat16 smg[];
    const int tid  = threadIdx.x;
    const int row0 = blockIdx.y * 128;
    const int col0 = blockIdx.x * 128;
    const int warp = tid >> 5;
    const int wm   = (warp & 1) * 64;
    const int wn   = (warp >> 1) * 32;

    FragC acc[4][2];
    int mi, ni;
#pragma unroll
    for (mi = 0; mi < 4; mi++)
#pragma unroll
        for (ni = 0; ni < 2; ni++)
            wmma::fill_fragment(acc[mi][ni], 0.f);

    g3_mainloop(smg, acc, Ahi, Alo, Bhi, Blo, row0, col0, N, K, tid, wm, wn);

#pragma unroll
    for (mi = 0; mi < 4; mi++) {
#pragma unroll
        for (ni = 0; ni < 2; ni++) {
            float* cp = C + (size_t)(row0 + wm + mi * 16) * N + col0 + wn + ni * 16;
            wmma::store_matrix_sync(cp, acc[mi][ni], N, wmma::mem_row_major);
        }
    }
}

__global__ __launch_bounds__(256, 2) void gemm_wmma3_split(
    const __nv_bfloat16* __restrict__ Ahi, const __nv_bfloat16* __restrict__ Alo,
    const __nv_bfloat16* __restrict__ Bhi, const __nv_bfloat16* __restrict__ Blo,
    __nv_bfloat16* __restrict__ Chi, __nv_bfloat16* __restrict__ Clo,
    int M, int N, int K)
{
    extern __shared__ __nv_bfloat16 smg[];
    const int tid  = threadIdx.x;
    const int row0 = blockIdx.y * 128;
    const int col0 = blockIdx.x * 128;
    const int warp = tid >> 5;
    const int wm   = (warp & 1) * 64;
    const int wn   = (warp >> 1) * 32;

    FragC acc[4][2];
    int mi, ni;
#pragma unroll
    for (mi = 0; mi < 4; mi++)
#pragma unroll
        for (ni = 0; ni < 2; ni++)
            wmma::fill_fragment(acc[mi][ni], 0.f);

    g3_mainloop(smg, acc, Ahi, Alo, Bhi, Blo, row0, col0, N, K, tid, wm, wn);

    __syncthreads();
    float* stg = (float*)smg;
#pragma unroll
    for (mi = 0; mi < 4; mi++) {
#pragma unroll
        for (ni = 0; ni < 2; ni++) {
            float* sp = stg + (wm + mi * 16) * 132 + wn + ni * 16;
            wmma::store_matrix_sync(sp, acc[mi][ni], 132, wmma::mem_row_major);
        }
    }
    __syncthreads();

    for (int c = tid; c < 4096; c += 256) {
        int r  = c >> 5;
        int q4 = c & 31;
        float4 v = *(const float4*)(stg + r * 132 + q4 * 4);
        float a0 = v.x;
        float a1 = v.y;
        float a2 = v.z;
        float a3 = v.w;
        __nv_bfloat16 h0 = __float2bfloat16(a0);
        __nv_bfloat16 h1 = __float2bfloat16(a1);
        __nv_bfloat16 h2 = __float2bfloat16(a2);
        __nv_bfloat16 h3 = __float2bfloat16(a3);
        __nv_bfloat16 l0 = __float2bfloat16(a0 - __bfloat162float(h0));
        __nv_bfloat16 l1 = __float2bfloat16(a1 - __bfloat162float(h1));
        __nv_bfloat16 l2 = __float2bfloat16(a2 - __bfloat162float(h2));
        __nv_bfloat16 l3 = __float2bfloat16(a3 - __bfloat162float(h3));
        __nv_bfloat16 hp[4];
        __nv_bfloat16 lp[4];
        hp[0] = h0; hp[1] = h1; hp[2] = h2; hp[3] = h3;
        lp[0] = l0; lp[1] = l1; lp[2] = l2; lp[3] = l3;
        size_t off = (size_t)(row0 + r) * N + col0 + q4 * 4;
        *(uint2*)(Chi + off) = *(uint2*)hp;
        *(uint2*)(Clo + off) = *(uint2*)lp;
    }
}

// ---------------------------------------------------------------------------
// Tensor-core flash attention, occ-3 version:
//  - P reuses K's smem (K is dead after QK^T; S-store barrier orders it)
//  - Q fragments reloaded from smem per tile (saves 64 regs)
// ---------------------------------------------------------------------------
__device__ __forceinline__ void ld_tile64(const __nv_bfloat16* __restrict__ g,
                                          int tok0, int ch,
                                          __nv_bfloat16* dst, int tid)
{
    int r = tid >> 2;
    int c = (tid & 3) * 16;
    const uint4* src = (const uint4*)(g + (size_t)(tok0 + r) * NQKV + ch + c);
    uint4* d = (uint4*)(dst + r * KV_LD + c);
    d[0] = src[0];
    d[1] = src[1];
}

__global__ __launch_bounds__(256, 3) void attn_wmma(
    const __nv_bfloat16* __restrict__ qh, const __nv_bfloat16* __restrict__ ql,
    __nv_bfloat16* __restrict__ yh, __nv_bfloat16* __restrict__ yl)
{
    extern __shared__ char sma[];
    __nv_bfloat16* Qh = (__nv_bfloat16*)(sma + OFF_QH);
    __nv_bfloat16* Ql = (__nv_bfloat16*)(sma + OFF_QL);
    __nv_bfloat16* Kh = (__nv_bfloat16*)(sma + OFF_KH);   // doubles as P_hi
    __nv_bfloat16* Kl = (__nv_bfloat16*)(sma + OFF_KL);   // doubles as P_lo
    __nv_bfloat16* Vh = (__nv_bfloat16*)(sma + OFF_VH);
    __nv_bfloat16* Vl = (__nv_bfloat16*)(sma + OFF_VL);
    float*         Ss = (float*)(sma + OFF_S);
    float*         Ls = (float*)(sma + OFF_L);

    const int qt   = (int)gridDim.x - 1 - (int)blockIdx.x;
    const int bh   = blockIdx.y;
    const int b    = bh >> 4;
    const int h    = bh & 15;
    const int q0   = qt * 64;
    const int tokb = b * Tn;
    const int tid  = threadIdx.x;
    const int warp = tid >> 5;
    const int wm   = (warp & 3) * 16;
    const int wn   = (warp >> 2) * 32;
    const int row  = tid >> 2;
    const int seg  = tid & 3;

    const int chq = h * HD;
    const int chk = Cn + h * HD;
    const int chv = 2 * Cn + h * HD;

    ld_tile64(qh, tokb + q0, chq, Qh, tid);
    ld_tile64(ql, tokb + q0, chq, Ql, tid);

    FragC of[2];
    wmma::fill_fragment(of[0], 0.f);
    wmma::fill_fragment(of[1], 0.f);
    float l_acc = 0.f;
    int ks;

    for (int kt = 0; kt <= qt; kt++) {
        const int k0 = kt * 64;
        __syncthreads();   // prior PV reads of P(=K bufs) and V done; Q ready (kt=0)
        ld_tile64(qh, tokb + k0, chk, Kh, tid);
        ld_tile64(ql, tokb + k0, chk, Kl, tid);
        ld_tile64(qh, tokb + k0, chv, Vh, tid);
        ld_tile64(ql, tokb + k0, chv, Vl, tid);
        __syncthreads();

        // S = Q @ K^T (3-pass); Q frags reloaded from smem
        FragC sf[2];
        wmma::fill_fragment(sf[0], 0.f);
        wmma::fill_fragment(sf[1], 0.f);
#pragma unroll
        for (ks = 0; ks < 4; ks++) {
            FragA qfh, qfl;
            wmma::load_matrix_sync(qfh, Qh + wm * KV_LD + ks * 16, KV_LD);
            wmma::load_matrix_sync(qfl, Ql + wm * KV_LD + ks * 16, KV_LD);
            FragBT kbh0, kbl0, kbh1, kbl1;
            wmma::load_matrix_sync(kbh0, Kh + (wn) * KV_LD + ks * 16, KV_LD);
            wmma::load_matrix_sync(kbh1, Kh + (wn + 16) * KV_LD + ks * 16, KV_LD);
            wmma::load_matrix_sync(kbl0, Kl + (wn) * KV_LD + ks * 16, KV_LD);
            wmma::load_matrix_sync(kbl1, Kl + (wn + 16) * KV_LD + ks * 16, KV_LD);
            wmma::mma_sync(sf[0], qfh, kbh0, sf[0]);
            wmma::mma_sync(sf[0], qfh, kbl0, sf[0]);
            wmma::mma_sync(sf[0], qfl, kbh0, sf[0]);
            wmma::mma_sync(sf[1], qfh, kbh1, sf[1]);
            wmma::mma_sync(sf[1], qfh, kbl1, sf[1]);
            wmma::mma_sync(sf[1], qfl, kbh1, sf[1]);
        }
        wmma::store_matrix_sync(Ss + wm * S_LD + wn, sf[0], S_LD, wmma::mem_row_major);
        wmma::store_matrix_sync(Ss + wm * S_LD + wn + 16, sf[1], S_LD, wmma::mem_row_major);
        __syncthreads();   // all K reads done; safe to overwrite K bufs with P

        // softmax: fixed-offset exp; P written into K's buffers
        float psum = 0.f;
        int c16;
#pragma unroll
        for (c16 = 0; c16 < 16; c16++) {
            int col = seg * 16 + c16;
            float sv = Ss[row * S_LD + col];
            float ex;
            if (kt == qt && col > row)
                ex = 0.f;
            else
                ex = __expf(0.125f * sv - 4.f);
            psum += ex;
            __nv_bfloat16 ph = __float2bfloat16(ex);
            Kh[row * KV_LD + col] = ph;
            Kl[row * KV_LD + col] = __float2bfloat16(ex - __bfloat162float(ph));
        }
        psum += __shfl_xor_sync(0xffffffffu, psum, 1);
        psum += __shfl_xor_sync(0xffffffffu, psum, 2);
        if (seg == 0)
            l_acc += psum;
        __syncthreads();

        // O += P @ V (3-pass)
#pragma unroll
        for (ks = 0; ks < 4; ks++) {
            FragA pfh, pfl;
            wmma::load_matrix_sync(pfh, Kh + wm * KV_LD + ks * 16, KV_LD);
            wmma::load_matrix_sync(pfl, Kl + wm * KV_LD + ks * 16, KV_LD);
            FragB vbh0, vbl0, vbh1, vbl1;
            wmma::load_matrix_sync(vbh0, Vh + (ks * 16) * KV_LD + wn, KV_LD);
            wmma::load_matrix_sync(vbh1, Vh + (ks * 16) * KV_LD + wn + 16, KV_LD);
            wmma::load_matrix_sync(vbl0, Vl + (ks * 16) * KV_LD + wn, KV_LD);
            wmma::load_matrix_sync(vbl1, Vl + (ks * 16) * KV_LD + wn + 16, KV_LD);
            wmma::mma_sync(of[0], pfh, vbh0, of[0]);
            wmma::mma_sync(of[0], pfh, vbl0, of[0]);
            wmma::mma_sync(of[0], pfl, vbh0, of[0]);
            wmma::mma_sync(of[1], pfh, vbh1, of[1]);
            wmma::mma_sync(of[1], pfh, vbl1, of[1]);
            wmma::mma_sync(of[1], pfl, vbh1, of[1]);
        }
    }

    __syncthreads();
    wmma::store_matrix_sync(Ss + wm * S_LD + wn, of[0], S_LD, wmma::mem_row_major);
    wmma::store_matrix_sync(Ss + wm * S_LD + wn + 16, of[1], S_LD, wmma::mem_row_major);
    if (seg == 0)
        Ls[row] = l_acc;
    __syncthreads();

    float inv = 1.f / Ls[row];
    size_t obase = (size_t)(tokb + q0 + row) * Cn + h * HD + seg * 16;
    int c16;
#pragma unroll
    for (c16 = 0; c16 < 16; c16++) {
        float v = Ss[row * S_LD + seg * 16 + c16] * inv;
        __nv_bfloat16 vh = __float2bfloat16(v);
        yh[obase + c16] = vh;
        yl[obase + c16] = __float2bfloat16(v - __bfloat162float(vh));
    }
}

// ---------------------------------------------------------------------------
extern "C" void kernel_launch(void* const* d_in, const int* in_sizes, int n_in,
                              void* d_out, int out_size)
{
    (void)in_sizes; (void)n_in; (void)out_size;
    const float* x      = (const float*)d_in[0];
    const float* w_qkv  = (const float*)d_in[1];
    const float* w_proj = (const float*)d_in[2];
    float* out = (float*)d_out;

    void* pqh = 0;
    void* pql = 0;
    void* pxh = 0;
    void* pxl = 0;
    void* pwh = 0;
    void* pwl = 0;
    void* pyh = 0;
    void* pyl = 0;
    void* pph = 0;
    void* ppl = 0;
    cudaGetSymbolAddress(&pqh, g_qkvh);
    cudaGetSymbolAddress(&pql, g_qkvl);
    cudaGetSymbolAddress(&pxh, g_xhi);
    cudaGetSymbolAddress(&pxl, g_xlo);
    cudaGetSymbolAddress(&pwh, g_whi);
    cudaGetSymbolAddress(&pwl, g_wlo);
    cudaGetSymbolAddress(&pyh, g_yhi);
    cudaGetSymbolAddress(&pyl, g_ylo);
    cudaGetSymbolAddress(&pph, g_phi);
    cudaGetSymbolAddress(&ppl, g_plo);

    cudaFuncSetAttribute(gemm_wmma3,
                         cudaFuncAttributeMaxDynamicSharedMemorySize, GEMM_SMEM);
    cudaFuncSetAttribute(gemm_wmma3_split,
                         cudaFuncAttributeMaxDynamicSharedMemorySize, GEMM_SMEM);
    cudaFuncSetAttribute(attn_wmma,
                         cudaFuncAttributeMaxDynamicSharedMemorySize, ATTN2_SMEM);

    int n4a = MTOK * Cn / 4;
    int n4b = Cn * NQKV / 4;
    int n4c = Cn * Cn / 4;

    split_bf16<<<(n4a + 255) / 256, 256>>>(x, (__nv_bfloat16*)pxh,
                                           (__nv_bfloat16*)pxl, n4a);
    split_bf16<<<(n4b + 255) / 256, 256>>>(w_qkv, (__nv_bfloat16*)pwh,
                                           (__nv_bfloat16*)pwl, n4b);

    dim3 g1(NQKV / 128, MTOK / 128);
    gemm_wmma3_split<<<g1, 256, GEMM_SMEM>>>(
        (__nv_bfloat16*)pxh, (__nv_bfloat16*)pxl,
        (__nv_bfloat16*)pwh, (__nv_bfloat16*)pwl,
        (__nv_bfloat16*)pqh, (__nv_bfloat16*)pql, MTOK, NQKV, Cn);

    dim3 g2(Tn / 64, Bn * Hn);
    attn_wmma<<<g2, 256, ATTN2_SMEM>>>((__nv_bfloat16*)pqh, (__nv_bfloat16*)pql,
                                       (__nv_bfloat16*)pyh, (__nv_bfloat16*)pyl);

    split_bf16<<<(n4c + 255) / 256, 256>>>(w_proj, (__nv_bfloat16*)pph,
                                           (__nv_bfloat16*)ppl, n4c);

    dim3 g3(Cn / 128, MTOK / 128);
    gemm_wmma3<<<g3, 256, GEMM_SMEM>>>((__nv_bfloat16*)pyh, (__nv_bfloat16*)pyl,
                                       (__nv_bfloat16*)pph, (__nv_bfloat16*)ppl,
                                       out, MTOK, Cn, Cn);
}